// round 9
// baseline (speedup 1.0000x reference)
#include <cuda_runtime.h>
#include <cuda_bf16.h>
#include <math.h>

#define CC 2048
#define GG 4
#define LL 512
#define NT 16384
#define EPSV 1e-4f
#define KS 16
#define KCH (NT/KS)
#define SQ_ITERS 12

typedef unsigned long long u64;

__device__ __forceinline__ u64 ffma2(u64 a, u64 b, u64 c) {
    u64 d;
    asm("fma.rn.f32x2 %0, %1, %2, %3;" : "=l"(d) : "l"(a), "l"(b), "l"(c));
    return d;
}
__device__ __forceinline__ u64 splat2(float x) {
    u64 d; unsigned xi = __float_as_uint(x);
    asm("mov.b64 %0, {%1, %2};" : "=l"(d) : "r"(xi), "r"(xi));
    return d;
}
__device__ __forceinline__ float2 unpk(u64 v) {
    unsigned lo, hi;
    asm("mov.b64 {%0, %1}, %2;" : "=r"(lo), "=r"(hi) : "l"(v));
    float2 r; r.x = __uint_as_float(lo); r.y = __uint_as_float(hi); return r;
}

struct ChainOp { int ida, idb, idc, mode, rs, ws; };

// ---------------- device scratch ----------------
__device__ float g_part[KS][GG][LL][LL];
__device__ float g_A[GG][LL][LL];
__device__ float g_Y[2][GG][LL][LL];
__device__ float g_Z[2][GG][LL][LL];
__device__ float g_T[GG][LL][LL];
__device__ float g_M[2][GG][LL][LL];
__device__ float g_P[GG][LL][LL];
__device__ float g_mu[CC];
__device__ float g_v[GG][LL];
__device__ float g_beta[CC];
__device__ float g_scal[16];          // [g]=RQ lam_max est, [8+g]=lam_min
__device__ float g_red2[2][GG][32];   // Frobenius^2 partials, ping-pong

__device__ __forceinline__ float* bufptr(int id) {
    switch (id) {
        case 0: return &g_Y[0][0][0][0];
        case 1: return &g_Y[1][0][0][0];
        case 2: return &g_Z[0][0][0][0];
        case 3: return &g_Z[1][0][0][0];
        case 4: return &g_T[0][0][0];
        case 5: return &g_M[0][0][0][0];
        case 6: return &g_M[1][0][0][0];
        default: return &g_A[0][0][0];
    }
}

// ---------------- per-channel mean ----------------
__global__ __launch_bounds__(256) void k_mean(const float* __restrict__ x) {
    __shared__ float sm[256];
    int c = blockIdx.x;
    const float4* row = (const float4*)(x + (size_t)c * NT);
    float s = 0.f;
    for (int i = threadIdx.x; i < NT / 4; i += 256) {
        float4 v = row[i];
        s += (v.x + v.y) + (v.z + v.w);
    }
    int t = threadIdx.x;
    sm[t] = s; __syncthreads();
    for (int o = 128; o > 0; o >>= 1) { if (t < o) sm[t] += sm[t + o]; __syncthreads(); }
    if (t == 0) g_mu[c] = sm[0] * (1.f / NT);
}

// ---------------- cov partials: lower-tri 128x128 tiles, split-K, FFMA2 (single buffer) ----------------
__global__ __launch_bounds__(256) void k_cov(const float* __restrict__ x) {
    __shared__ float As[32][132];
    __shared__ float Bs[32][132];
    const int TIa[10] = {0,1,1,2,2,2,3,3,3,3};
    const int TJa[10] = {0,0,1,0,1,2,0,1,2,3};
    int ti = TIa[blockIdx.x], tj = TJa[blockIdx.x];
    int g = blockIdx.y, sp = blockIdx.z;
    const float* Ab = x + (size_t)(g * LL + ti * 128) * NT + sp * KCH;
    const float* Bb = x + (size_t)(g * LL + tj * 128) * NT + sp * KCH;
    int t = threadIdx.x, tx = t & 15, ty = t >> 4;
    u64 acc[4][8];
    #pragma unroll
    for (int u = 0; u < 4; u++)
        #pragma unroll
        for (int w = 0; w < 8; w++) acc[u][w] = 0ull;
    for (int kb = 0; kb < KCH; kb += 32) {
        __syncthreads();
        #pragma unroll
        for (int q = 0; q < 4; q++) {
            int idx = t + 256 * q;
            int r = idx >> 3, c4 = (idx & 7) << 2;
            float4 av = *(const float4*)(Ab + (size_t)r * NT + kb + c4);
            As[c4][r] = av.x; As[c4+1][r] = av.y; As[c4+2][r] = av.z; As[c4+3][r] = av.w;
            float4 bv = *(const float4*)(Bb + (size_t)r * NT + kb + c4);
            Bs[c4][r] = bv.x; Bs[c4+1][r] = bv.y; Bs[c4+2][r] = bv.z; Bs[c4+3][r] = bv.w;
        }
        __syncthreads();
        #pragma unroll
        for (int k = 0; k < 32; k++) {
            ulonglong2 a0 = *(const ulonglong2*)&As[k][ty * 8];
            ulonglong2 a1 = *(const ulonglong2*)&As[k][ty * 8 + 4];
            float4 b0 = *(const float4*)&Bs[k][tx * 8];
            float4 b1 = *(const float4*)&Bs[k][tx * 8 + 4];
            u64 s0 = splat2(b0.x), s1 = splat2(b0.y), s2 = splat2(b0.z), s3 = splat2(b0.w);
            u64 s4 = splat2(b1.x), s5 = splat2(b1.y), s6 = splat2(b1.z), s7 = splat2(b1.w);
            u64 ar[4] = {a0.x, a0.y, a1.x, a1.y};
            #pragma unroll
            for (int u = 0; u < 4; u++) {
                acc[u][0] = ffma2(ar[u], s0, acc[u][0]);
                acc[u][1] = ffma2(ar[u], s1, acc[u][1]);
                acc[u][2] = ffma2(ar[u], s2, acc[u][2]);
                acc[u][3] = ffma2(ar[u], s3, acc[u][3]);
                acc[u][4] = ffma2(ar[u], s4, acc[u][4]);
                acc[u][5] = ffma2(ar[u], s5, acc[u][5]);
                acc[u][6] = ffma2(ar[u], s6, acc[u][6]);
                acc[u][7] = ffma2(ar[u], s7, acc[u][7]);
            }
        }
    }
    #pragma unroll
    for (int u = 0; u < 4; u++) {
        int ia = ti * 128 + ty * 8 + 2 * u;
        int jb = tj * 128 + tx * 8;
        float2 f[8];
        #pragma unroll
        for (int w = 0; w < 8; w++) f[w] = unpk(acc[u][w]);
        *(float4*)&g_part[sp][g][ia][jb]     = make_float4(f[0].x, f[1].x, f[2].x, f[3].x);
        *(float4*)&g_part[sp][g][ia][jb + 4] = make_float4(f[4].x, f[5].x, f[6].x, f[7].x);
        *(float4*)&g_part[sp][g][ia + 1][jb]     = make_float4(f[0].y, f[1].y, f[2].y, f[3].y);
        *(float4*)&g_part[sp][g][ia + 1][jb + 4] = make_float4(f[4].y, f[5].y, f[6].y, f[7].y);
    }
}

// ---------------- reduce partials -> A ----------------
__global__ __launch_bounds__(256) void k_cov_reduce() {
    int g = blockIdx.y;
    int idx = blockIdx.x * 256 + threadIdx.x;
    int i = idx >> 9, j = idx & 511;
    if (i < j) return;
    float s = 0.f;
    #pragma unroll
    for (int sp = 0; sp < KS; sp++) s += g_part[sp][g][i][j];
    float v = s * (1.f / NT) - g_mu[g * LL + i] * g_mu[g * LL + j];
    if (i == j) v += EPSV;
    g_A[g][i][j] = v;
    g_A[g][j][i] = v;
}

// ---------------- fused power iteration: 1 block per group, 7 matvecs + RQ ----------------
__global__ __launch_bounds__(512) void k_pi() {
    int g = blockIdx.x, j = threadIdx.x;
    __shared__ float vs[512];
    __shared__ float r1[512], r2[512];
    const float* Ac = &g_A[g][0][0];
    unsigned h = (unsigned)(g * LL + j) * 1103515245u + 12345u;
    float vj = 0.5f + (float)(h & 1023u) * (1.0f / 1024.0f);
    vs[j] = vj;
    __syncthreads();
    float uj = 0.f;
    for (int it = 0; it < 7; it++) {
        uj = 0.f;
        #pragma unroll 8
        for (int k = 0; k < LL; k++) uj = fmaf(Ac[(size_t)k * LL + j], vs[k], uj);
        __syncthreads();
        if (it < 6) {
            vs[j] = uj;
            __syncthreads();
        }
    }
    vj = vs[j];
    r1[j] = vj * uj; r2[j] = vj * vj;
    __syncthreads();
    for (int o = 256; o > 0; o >>= 1) {
        if (j < o) { r1[j] += r1[j + o]; r2[j] += r2[j + o]; }
        __syncthreads();
    }
    if (j == 0) g_scal[g] = r1[0] / r2[0];
}

// ---------------- prep: Y0 = A/c ; T0(->Z[0]) = 1.5I-0.5Y0 ; M0 = sigma I - A + fnorm ----------------
__global__ __launch_bounds__(256) void k_prep() {
    int g = blockIdx.y;
    float rq = g_scal[g];
    float invc = 1.0f / (1.05f * rq);
    float sigma = 1.15f * rq;
    int base = blockIdx.x * 8192;
    float ss = 0.f;
    for (int q = 0; q < 32; q++) {
        int idx = base + threadIdx.x + 256 * q;
        int i = idx >> 9, j = idx & 511;
        float a = g_A[g][i][j];
        float y = a * invc;
        g_Y[0][g][i][j] = y;
        g_Z[0][g][i][j] = (i == j ? 1.5f : 0.0f) - 0.5f * y;
        float m = (i == j ? sigma : 0.0f) - a;
        g_M[0][g][i][j] = m;
        ss += m * m;
    }
    __shared__ float rsm[256];
    int t = threadIdx.x;
    rsm[t] = ss; __syncthreads();
    for (int o = 128; o > 0; o >>= 1) { if (t < o) rsm[t] += rsm[t + o]; __syncthreads(); }
    if (t == 0) g_red2[0][g][blockIdx.x] = rsm[0];
}

// ---------------- combined chain GEMM (single-buffer body, 3 ops per launch) ----------------
// mode 0: C = 1.5 I - 0.5 (A B) ; mode 1: C = A B ;
// mode 2: C = (A B) * rsqrt(sum g_red2[rs]); block sumsq -> g_red2[ws]
__global__ __launch_bounds__(256) void k_chain(ChainOp o0, ChainOp o1, ChainOp o2) {
    int opi = blockIdx.z >> 2;
    int g = blockIdx.z & 3;
    ChainOp op = (opi == 0) ? o0 : (opi == 1 ? o1 : o2);
    const float* A = bufptr(op.ida) + (size_t)g * LL * LL;
    const float* B = bufptr(op.idb) + (size_t)g * LL * LL;
    float* C = bufptr(op.idc) + (size_t)g * LL * LL;
    __shared__ float As[32][132];
    __shared__ float Bs[32][68];
    __shared__ float rsm[256];
    int t = threadIdx.x, tx = t & 15, ty = t >> 4;
    int i0 = blockIdx.y * 128, j0 = blockIdx.x * 64;
    float scale = 1.0f;
    if (op.mode == 2) {
        float fs = 0.f;
        #pragma unroll
        for (int q = 0; q < 32; q++) fs += g_red2[op.rs][g][q];
        scale = rsqrtf(fs);
    }
    u64 acc[4][4];
    #pragma unroll
    for (int u = 0; u < 4; u++)
        #pragma unroll
        for (int w = 0; w < 4; w++) acc[u][w] = 0ull;
    for (int kb = 0; kb < 512; kb += 32) {
        __syncthreads();
        #pragma unroll
        for (int q = 0; q < 4; q++) {
            int idx = t + 256 * q;
            int r = idx >> 3, c4 = (idx & 7) << 2;
            float4 av = *(const float4*)(A + (size_t)(i0 + r) * 512 + kb + c4);
            As[c4][r] = av.x; As[c4+1][r] = av.y; As[c4+2][r] = av.z; As[c4+3][r] = av.w;
        }
        #pragma unroll
        for (int q = 0; q < 2; q++) {
            int idx = t + 256 * q;
            int r2 = idx >> 4, d4 = (idx & 15) << 2;
            *(float4*)&Bs[r2][d4] = *(const float4*)(B + (size_t)(kb + r2) * 512 + j0 + d4);
        }
        __syncthreads();
        #pragma unroll
        for (int k = 0; k < 32; k++) {
            ulonglong2 a0 = *(const ulonglong2*)&As[k][ty * 8];
            ulonglong2 a1 = *(const ulonglong2*)&As[k][ty * 8 + 4];
            float4 bf = *(const float4*)&Bs[k][tx * 4];
            u64 s0 = splat2(bf.x), s1 = splat2(bf.y), s2 = splat2(bf.z), s3 = splat2(bf.w);
            u64 ar[4] = {a0.x, a0.y, a1.x, a1.y};
            #pragma unroll
            for (int u = 0; u < 4; u++) {
                acc[u][0] = ffma2(ar[u], s0, acc[u][0]);
                acc[u][1] = ffma2(ar[u], s1, acc[u][1]);
                acc[u][2] = ffma2(ar[u], s2, acc[u][2]);
                acc[u][3] = ffma2(ar[u], s3, acc[u][3]);
            }
        }
    }
    float ss = 0.f;
    #pragma unroll
    for (int u = 0; u < 4; u++) {
        int gia = i0 + ty * 8 + 2 * u;
        int gj = j0 + tx * 4;
        float2 f[4];
        #pragma unroll
        for (int w = 0; w < 4; w++) f[w] = unpk(acc[u][w]);
        float lo[4], hi[4];
        #pragma unroll
        for (int w = 0; w < 4; w++) {
            float va = f[w].x, vb = f[w].y;
            if (op.mode == 0) {
                va = (gia == gj + w ? 1.5f : 0.0f) - 0.5f * va;
                vb = (gia + 1 == gj + w ? 1.5f : 0.0f) - 0.5f * vb;
            } else if (op.mode == 2) {
                va *= scale; vb *= scale;
                ss += va * va + vb * vb;
            }
            lo[w] = va; hi[w] = vb;
        }
        *(float4*)&C[(size_t)gia * 512 + gj] = make_float4(lo[0], lo[1], lo[2], lo[3]);
        *(float4*)&C[(size_t)(gia + 1) * 512 + gj] = make_float4(hi[0], hi[1], hi[2], hi[3]);
    }
    if (op.mode == 2) {
        rsm[t] = ss; __syncthreads();
        for (int o = 128; o > 0; o >>= 1) { if (t < o) rsm[t] += rsm[t + o]; __syncthreads(); }
        if (t == 0) g_red2[op.ws][g][blockIdx.y * 8 + blockIdx.x] = rsm[0];
    }
}

// ---------------- eigen extraction: colnorm + rayleigh fused ----------------
__global__ void k_eig() {
    int g = blockIdx.x, j = threadIdx.x;
    const float* M = &g_M[0][g][0][0];
    float s = 0.f;
    #pragma unroll 8
    for (int i = 0; i < LL; i++) { float m = M[(size_t)i * LL + j]; s += m * m; }
    __shared__ float sv[512]; __shared__ int si[512];
    sv[j] = s; si[j] = j; __syncthreads();
    for (int o = 256; o > 0; o >>= 1) {
        if (j < o) { if (sv[j + o] > sv[j]) { sv[j] = sv[j + o]; si[j] = si[j + o]; } }
        __syncthreads();
    }
    int jm = si[0];
    float inv = rsqrtf(sv[0]);
    __shared__ float vs[512];
    float vj = M[(size_t)j * LL + jm] * inv;
    vs[j] = vj;
    g_v[g][j] = vj;
    __syncthreads();
    float u = 0.f;
    const float* Ac = &g_A[g][0][0];
    #pragma unroll 8
    for (int k = 0; k < LL; k++) u = fmaf(Ac[(size_t)k * LL + j], vs[k], u);
    __shared__ float r1[512];
    r1[j] = u * vj; __syncthreads();
    for (int o = 256; o > 0; o >>= 1) {
        if (j < o) r1[j] += r1[j + o];
        __syncthreads();
    }
    if (j == 0) g_scal[8 + g] = r1[0];
}

// ---------------- P = Z/sqrt(c) - lam^{-1/2} v v^T ----------------
__global__ __launch_bounds__(256) void k_subspace(int zid) {
    int g = blockIdx.y;
    int idx = blockIdx.x * 256 + threadIdx.x;
    int i = idx >> 9, j = idx & 511;
    const float* Z = bufptr(zid) + (size_t)g * LL * LL;
    float c = 1.05f * g_scal[g];
    float lam = g_scal[8 + g];
    g_P[g][i][j] = Z[(size_t)i * 512 + j] * rsqrtf(c) - rsqrtf(lam) * g_v[g][i] * g_v[g][j];
}

// ---------------- beta = bias - w * (P mu) ----------------
__global__ void k_beta(const float* __restrict__ w, const float* __restrict__ b) {
    int g = blockIdx.x, i = threadIdx.x;
    __shared__ float mus[512];
    mus[i] = g_mu[g * LL + i]; __syncthreads();
    float s = 0.f;
    const float* Pc = &g_P[g][0][0];
    #pragma unroll 8
    for (int k = 0; k < 512; k++) s = fmaf(Pc[(size_t)k * 512 + i], mus[k], s);
    int c = g * LL + i;
    g_beta[c] = b[c] - w[c] * s;
}

// ---------------- apply: out = w * (P X) + beta, FFMA2 (single buffer) ----------------
__global__ __launch_bounds__(256) void k_apply(const float* __restrict__ x,
                                               const float* __restrict__ w,
                                               float* __restrict__ out) {
    int g = blockIdx.z;
    int i0 = blockIdx.y * 128;
    int j0 = blockIdx.x * 128;
    __shared__ float As[32][132];
    __shared__ float Bs[32][132];
    int t = threadIdx.x, tx = t & 15, ty = t >> 4;
    const float* P = &g_P[g][0][0];
    const float* X = x + (size_t)(g * LL) * NT;
    u64 acc[4][8];
    #pragma unroll
    for (int u = 0; u < 4; u++)
        #pragma unroll
        for (int wv = 0; wv < 8; wv++) acc[u][wv] = 0ull;
    for (int kb = 0; kb < 512; kb += 32) {
        __syncthreads();
        #pragma unroll
        for (int q = 0; q < 4; q++) {
            int idx = t + 256 * q;
            int r = idx >> 3, c4 = (idx & 7) << 2;
            float4 av = *(const float4*)(P + (size_t)(i0 + r) * 512 + kb + c4);
            As[c4][r] = av.x; As[c4+1][r] = av.y; As[c4+2][r] = av.z; As[c4+3][r] = av.w;
            int r2 = idx >> 5, d4 = (idx & 31) << 2;
            *(float4*)(&Bs[r2][d4]) =
                *(const float4*)(X + (size_t)(kb + r2) * NT + j0 + d4);
        }
        __syncthreads();
        #pragma unroll
        for (int k = 0; k < 32; k++) {
            ulonglong2 a0 = *(const ulonglong2*)&As[k][ty * 8];
            ulonglong2 a1 = *(const ulonglong2*)&As[k][ty * 8 + 4];
            float4 b0 = *(const float4*)&Bs[k][tx * 8];
            float4 b1 = *(const float4*)&Bs[k][tx * 8 + 4];
            u64 s0 = splat2(b0.x), s1 = splat2(b0.y), s2 = splat2(b0.z), s3 = splat2(b0.w);
            u64 s4 = splat2(b1.x), s5 = splat2(b1.y), s6 = splat2(b1.z), s7 = splat2(b1.w);
            u64 ar[4] = {a0.x, a0.y, a1.x, a1.y};
            #pragma unroll
            for (int u = 0; u < 4; u++) {
                acc[u][0] = ffma2(ar[u], s0, acc[u][0]);
                acc[u][1] = ffma2(ar[u], s1, acc[u][1]);
                acc[u][2] = ffma2(ar[u], s2, acc[u][2]);
                acc[u][3] = ffma2(ar[u], s3, acc[u][3]);
                acc[u][4] = ffma2(ar[u], s4, acc[u][4]);
                acc[u][5] = ffma2(ar[u], s5, acc[u][5]);
                acc[u][6] = ffma2(ar[u], s6, acc[u][6]);
                acc[u][7] = ffma2(ar[u], s7, acc[u][7]);
            }
        }
    }
    #pragma unroll
    for (int u = 0; u < 4; u++) {
        int cha = g * LL + i0 + ty * 8 + 2 * u;
        float wa = w[cha], ba = g_beta[cha];
        float wb = w[cha + 1], bb = g_beta[cha + 1];
        float2 f[8];
        #pragma unroll
        for (int wv = 0; wv < 8; wv++) f[wv] = unpk(acc[u][wv]);
        float* orow_a = out + (size_t)cha * NT + j0 + tx * 8;
        float* orow_b = out + (size_t)(cha + 1) * NT + j0 + tx * 8;
        float4 va0, va1, vb0, vb1;
        va0.x = fmaf(wa, f[0].x, ba); va0.y = fmaf(wa, f[1].x, ba);
        va0.z = fmaf(wa, f[2].x, ba); va0.w = fmaf(wa, f[3].x, ba);
        va1.x = fmaf(wa, f[4].x, ba); va1.y = fmaf(wa, f[5].x, ba);
        va1.z = fmaf(wa, f[6].x, ba); va1.w = fmaf(wa, f[7].x, ba);
        vb0.x = fmaf(wb, f[0].y, bb); vb0.y = fmaf(wb, f[1].y, bb);
        vb0.z = fmaf(wb, f[2].y, bb); vb0.w = fmaf(wb, f[3].y, bb);
        vb1.x = fmaf(wb, f[4].y, bb); vb1.y = fmaf(wb, f[5].y, bb);
        vb1.z = fmaf(wb, f[6].y, bb); vb1.w = fmaf(wb, f[7].y, bb);
        *(float4*)(orow_a) = va0; *(float4*)(orow_a + 4) = va1;
        *(float4*)(orow_b) = vb0; *(float4*)(orow_b + 4) = vb1;
    }
}

// ---------------- launch ----------------
extern "C" void kernel_launch(void* const* d_in, const int* in_sizes, int n_in,
                              void* d_out, int out_size) {
    const float* x = (const float*)d_in[0];
    const float* w = (const float*)d_in[1];
    const float* b = (const float*)d_in[2];
    float* out = (float*)d_out;

    k_mean<<<CC, 256>>>(x);
    k_cov<<<dim3(10, GG, KS), 256>>>(x);
    k_cov_reduce<<<dim3(1024, GG), 256>>>();

    k_pi<<<GG, 512>>>();
    k_prep<<<dim3(32, GG), 256>>>();   // Y0->0, T0->2, M0->5 + fnorm partials

    // NS ops (buffers: 0=Y[0] 1=Y[1] 2=Z[0] 3=Z[1] 4=T) and SQ ops interleaved.
    ChainOp ns1 = {0, 2, 1, 1, 0, 0};   // Y1 = Y0 T0
    ChainOp ns2 = {2, 1, 4, 0, 0, 0};   // T  = 1.5I - 0.5 Z1 Y1
    ChainOp ns3a = {1, 4, 0, 1, 0, 0};  // Y2
    ChainOp ns3b = {4, 2, 3, 1, 0, 0};  // Z2
    ChainOp ns4 = {3, 0, 4, 0, 0, 0};   // T
    ChainOp ns5a = {0, 4, 1, 1, 0, 0};  // Y3
    ChainOp ns5b = {4, 3, 2, 1, 0, 0};  // Z3
    ChainOp ns6 = {2, 1, 4, 0, 0, 0};   // T
    ChainOp ns7 = {4, 2, 3, 1, 0, 0};   // Z4 (final -> buf 3)
    ChainOp sq[SQ_ITERS];
    for (int k = 0; k < SQ_ITERS; k++) {
        ChainOp o = {5 + (k & 1), 5 + (k & 1), 5 + 1 - (k & 1), 2, k & 1, 1 - (k & 1)};
        sq[k] = o;
    }
    ChainOp dummy = {7, 7, 4, 1, 0, 0};

    k_chain<<<dim3(8, 4, 8),  256>>>(ns1, sq[0], dummy);
    k_chain<<<dim3(8, 4, 8),  256>>>(ns2, sq[1], dummy);
    k_chain<<<dim3(8, 4, 12), 256>>>(ns3a, ns3b, sq[2]);
    k_chain<<<dim3(8, 4, 8),  256>>>(ns4, sq[3], dummy);
    k_chain<<<dim3(8, 4, 12), 256>>>(ns5a, ns5b, sq[4]);
    k_chain<<<dim3(8, 4, 8),  256>>>(ns6, sq[5], dummy);
    k_chain<<<dim3(8, 4, 8),  256>>>(ns7, sq[6], dummy);
    for (int k = 7; k < SQ_ITERS; k++)
        k_chain<<<dim3(8, 4, 4), 256>>>(sq[k], dummy, dummy);

    k_eig<<<GG, 512>>>();
    k_subspace<<<dim3(1024, GG), 256>>>(3);
    k_beta<<<GG, 512>>>(w, b);
    k_apply<<<dim3(128, 4, GG), 256>>>(x, w, out);
}

// round 11
// speedup vs baseline: 1.2729x; 1.2729x over previous
#include <cuda_runtime.h>
#include <cuda_bf16.h>
#include <math.h>

#define CC 2048
#define GG 4
#define LL 512
#define NT 16384
#define EPSV 1e-4f
#define KS 16
#define KCH (NT/KS)
#define SQ_ITERS 12

typedef unsigned long long u64;
typedef unsigned int u32;

// ================= FFMA2 helpers =================
__device__ __forceinline__ u64 ffma2(u64 a, u64 b, u64 c) {
    u64 d;
    asm("fma.rn.f32x2 %0, %1, %2, %3;" : "=l"(d) : "l"(a), "l"(b), "l"(c));
    return d;
}
__device__ __forceinline__ u64 splat2(float x) {
    u64 d; unsigned xi = __float_as_uint(x);
    asm("mov.b64 %0, {%1, %2};" : "=l"(d) : "r"(xi), "r"(xi));
    return d;
}
__device__ __forceinline__ float2 unpk(u64 v) {
    unsigned lo, hi;
    asm("mov.b64 {%0, %1}, %2;" : "=r"(lo), "=r"(hi) : "l"(v));
    float2 r; r.x = __uint_as_float(lo); r.y = __uint_as_float(hi); return r;
}

// ================= mma.sync / ldmatrix helpers (base ISA, no 'a' features) =================
__device__ __forceinline__ u32 smem_u32(const void* p) {
    u32 a;
    asm("{ .reg .u64 t; cvta.to.shared.u64 t, %1; cvt.u32.u64 %0, t; }" : "=r"(a) : "l"(p));
    return a;
}
__device__ __forceinline__ void ldsm_x4(u32& r0, u32& r1, u32& r2, u32& r3, u32 addr) {
    asm volatile("ldmatrix.sync.aligned.m8n8.x4.shared.b16 {%0,%1,%2,%3}, [%4];"
                 : "=r"(r0), "=r"(r1), "=r"(r2), "=r"(r3) : "r"(addr));
}
__device__ __forceinline__ void ldsm_x2(u32& r0, u32& r1, u32 addr) {
    asm volatile("ldmatrix.sync.aligned.m8n8.x2.shared.b16 {%0,%1}, [%2];"
                 : "=r"(r0), "=r"(r1) : "r"(addr));
}
__device__ __forceinline__ void mma_bf16(float* c, u32 a0, u32 a1, u32 a2, u32 a3,
                                         u32 b0, u32 b1) {
    asm volatile(
        "mma.sync.aligned.m16n8k16.row.col.f32.bf16.bf16.f32 "
        "{%0,%1,%2,%3}, {%4,%5,%6,%7}, {%8,%9}, {%0,%1,%2,%3};"
        : "+f"(c[0]), "+f"(c[1]), "+f"(c[2]), "+f"(c[3])
        : "r"(a0), "r"(a1), "r"(a2), "r"(a3), "r"(b0), "r"(b1));
}

// ================= device scratch =================
__device__ float g_part[KS][GG][LL][LL];
__device__ float g_A[GG][LL][LL];
__device__ float g_Y[2][GG][LL][LL];
__device__ float g_Z[2][GG][LL][LL];
__device__ float g_T[GG][LL][LL];
__device__ float g_M[2][GG][LL][LL];
__device__ float g_P[GG][LL][LL];
__device__ float g_mu[CC];
__device__ float g_pv[2][GG][LL];
__device__ float g_v[GG][LL];
__device__ float g_beta[CC];
__device__ float g_scal[16];
__device__ float g_red2[2][GG][32];
// bf16 split operands for the mma apply
__device__ __nv_bfloat16 gXT_hi[(size_t)GG * NT * LL];
__device__ __nv_bfloat16 gXT_lo[(size_t)GG * NT * LL];
__device__ __nv_bfloat16 gP_hi[GG][LL][LL];
__device__ __nv_bfloat16 gP_lo[GG][LL][LL];

__device__ __forceinline__ float* bufptr(int id) {
    switch (id) {
        case 0: return &g_Y[0][0][0][0];
        case 1: return &g_Y[1][0][0][0];
        case 2: return &g_Z[0][0][0][0];
        case 3: return &g_Z[1][0][0][0];
        case 4: return &g_T[0][0][0];
        case 5: return &g_M[0][0][0][0];
        case 6: return &g_M[1][0][0][0];
        default: return &g_A[0][0][0];
    }
}

// ================= mean =================
__global__ __launch_bounds__(256) void k_mean(const float* __restrict__ x) {
    __shared__ float sm[256];
    int c = blockIdx.x;
    const float4* row = (const float4*)(x + (size_t)c * NT);
    float s = 0.f;
    for (int i = threadIdx.x; i < NT / 4; i += 256) {
        float4 v = row[i];
        s += (v.x + v.y) + (v.z + v.w);
    }
    int t = threadIdx.x;
    sm[t] = s; __syncthreads();
    for (int o = 128; o > 0; o >>= 1) { if (t < o) sm[t] += sm[t + o]; __syncthreads(); }
    if (t == 0) g_mu[c] = sm[0] * (1.f / NT);
}

// ================= X -> transposed bf16 hi/lo =================
__global__ __launch_bounds__(256) void k_cvt(const float* __restrict__ x) {
    __shared__ float ts[32][129];
    int g = blockIdx.z, k0 = blockIdx.y * 32, n0 = blockIdx.x * 128;
    int t = threadIdx.x;
    #pragma unroll
    for (int q = 0; q < 16; q++) {
        int idx = t + 256 * q;
        int r = idx >> 7, c = idx & 127;
        ts[r][c] = x[(size_t)(g * LL + k0 + r) * NT + n0 + c];
    }
    __syncthreads();
    #pragma unroll
    for (int q = 0; q < 2; q++) {
        int task = t + 256 * q;
        int n = task >> 2, oct = task & 3;
        union { unsigned short s[8]; uint4 v; } ph, pl;
        #pragma unroll
        for (int e = 0; e < 8; e++) {
            float vv = ts[oct * 8 + e][n];
            __nv_bfloat16 h = __float2bfloat16(vv);
            float hf = __bfloat162float(h);
            __nv_bfloat16 l = __float2bfloat16(vv - hf);
            ph.s[e] = *(unsigned short*)&h;
            pl.s[e] = *(unsigned short*)&l;
        }
        size_t dst = (size_t)(g * NT + n0 + n) * LL + k0 + oct * 8;
        *(uint4*)&gXT_hi[dst] = ph.v;
        *(uint4*)&gXT_lo[dst] = pl.v;
    }
}

// ================= cov partials: fp32 FFMA2 (round-5 proven) =================
__global__ __launch_bounds__(256) void k_cov(const float* __restrict__ x) {
    __shared__ float As[32][132];
    __shared__ float Bs[32][132];
    const int TIa[10] = {0,1,1,2,2,2,3,3,3,3};
    const int TJa[10] = {0,0,1,0,1,2,0,1,2,3};
    int ti = TIa[blockIdx.x], tj = TJa[blockIdx.x];
    int g = blockIdx.y, sp = blockIdx.z;
    const float* Ab = x + (size_t)(g * LL + ti * 128) * NT + sp * KCH;
    const float* Bb = x + (size_t)(g * LL + tj * 128) * NT + sp * KCH;
    int t = threadIdx.x, tx = t & 15, ty = t >> 4;
    u64 acc[4][8];
    #pragma unroll
    for (int u = 0; u < 4; u++)
        #pragma unroll
        for (int w = 0; w < 8; w++) acc[u][w] = 0ull;
    for (int kb = 0; kb < KCH; kb += 32) {
        __syncthreads();
        #pragma unroll
        for (int q = 0; q < 4; q++) {
            int idx = t + 256 * q;
            int r = idx >> 3, c4 = (idx & 7) << 2;
            float4 av = *(const float4*)(Ab + (size_t)r * NT + kb + c4);
            As[c4][r] = av.x; As[c4+1][r] = av.y; As[c4+2][r] = av.z; As[c4+3][r] = av.w;
            float4 bv = *(const float4*)(Bb + (size_t)r * NT + kb + c4);
            Bs[c4][r] = bv.x; Bs[c4+1][r] = bv.y; Bs[c4+2][r] = bv.z; Bs[c4+3][r] = bv.w;
        }
        __syncthreads();
        #pragma unroll
        for (int k = 0; k < 32; k++) {
            ulonglong2 a0 = *(const ulonglong2*)&As[k][ty * 8];
            ulonglong2 a1 = *(const ulonglong2*)&As[k][ty * 8 + 4];
            float4 b0 = *(const float4*)&Bs[k][tx * 8];
            float4 b1 = *(const float4*)&Bs[k][tx * 8 + 4];
            u64 s0 = splat2(b0.x), s1 = splat2(b0.y), s2 = splat2(b0.z), s3 = splat2(b0.w);
            u64 s4 = splat2(b1.x), s5 = splat2(b1.y), s6 = splat2(b1.z), s7 = splat2(b1.w);
            u64 ar[4] = {a0.x, a0.y, a1.x, a1.y};
            #pragma unroll
            for (int u = 0; u < 4; u++) {
                acc[u][0] = ffma2(ar[u], s0, acc[u][0]);
                acc[u][1] = ffma2(ar[u], s1, acc[u][1]);
                acc[u][2] = ffma2(ar[u], s2, acc[u][2]);
                acc[u][3] = ffma2(ar[u], s3, acc[u][3]);
                acc[u][4] = ffma2(ar[u], s4, acc[u][4]);
                acc[u][5] = ffma2(ar[u], s5, acc[u][5]);
                acc[u][6] = ffma2(ar[u], s6, acc[u][6]);
                acc[u][7] = ffma2(ar[u], s7, acc[u][7]);
            }
        }
    }
    #pragma unroll
    for (int u = 0; u < 4; u++) {
        int ia = ti * 128 + ty * 8 + 2 * u;
        int jb = tj * 128 + tx * 8;
        float2 f[8];
        #pragma unroll
        for (int w = 0; w < 8; w++) f[w] = unpk(acc[u][w]);
        *(float4*)&g_part[sp][g][ia][jb]     = make_float4(f[0].x, f[1].x, f[2].x, f[3].x);
        *(float4*)&g_part[sp][g][ia][jb + 4] = make_float4(f[4].x, f[5].x, f[6].x, f[7].x);
        *(float4*)&g_part[sp][g][ia + 1][jb]     = make_float4(f[0].y, f[1].y, f[2].y, f[3].y);
        *(float4*)&g_part[sp][g][ia + 1][jb + 4] = make_float4(f[4].y, f[5].y, f[6].y, f[7].y);
    }
}

// ================= reduce partials -> A =================
__global__ __launch_bounds__(256) void k_cov_reduce() {
    int g = blockIdx.y;
    int idx = blockIdx.x * 256 + threadIdx.x;
    int i = idx >> 9, j = idx & 511;
    if (i < j) return;
    float s = 0.f;
    #pragma unroll
    for (int sp = 0; sp < KS; sp++) s += g_part[sp][g][i][j];
    float v = s * (1.f / NT) - g_mu[g * LL + i] * g_mu[g * LL + j];
    if (i == j) v += EPSV;
    g_A[g][i][j] = v;
    g_A[g][j][i] = v;
}

// ================= power iteration =================
__global__ void k_pi_init() {
    int idx = blockIdx.x * 256 + threadIdx.x;
    if (idx < GG * LL) {
        unsigned h = (unsigned)idx * 1103515245u + 12345u;
        ((float*)g_pv)[idx] = 0.5f + (float)(h & 1023u) * (1.0f / 1024.0f);
    }
}

__global__ __launch_bounds__(256) void k_matvec(int inb) {
    int g = blockIdx.y;
    __shared__ float vs[LL];
    for (int i = threadIdx.x; i < LL; i += 256) vs[i] = g_pv[inb][g][i];
    __syncthreads();
    int warp = threadIdx.x >> 5, lane = threadIdx.x & 31;
    int row0 = blockIdx.x * 32 + warp * 4;
    for (int r = 0; r < 4; r++) {
        int i = row0 + r;
        const float* Ar = &g_A[g][i][0];
        float s = 0.f;
        for (int k = lane; k < LL; k += 32) s += Ar[k] * vs[k];
        #pragma unroll
        for (int o = 16; o > 0; o >>= 1) s += __shfl_down_sync(0xffffffffu, s, o);
        if (lane == 0) g_pv[1 - inb][g][i] = s;
    }
}

__global__ void k_rq() {
    int g = blockIdx.x, i = threadIdx.x;
    __shared__ float r1[512], r2[512];
    float v = g_pv[0][g][i], u = g_pv[1][g][i];
    r1[i] = v * u; r2[i] = v * v; __syncthreads();
    for (int o = 256; o > 0; o >>= 1) {
        if (i < o) { r1[i] += r1[i + o]; r2[i] += r2[i + o]; }
        __syncthreads();
    }
    if (i == 0) g_scal[g] = r1[0] / r2[0];
}

// ================= NS init =================
__global__ __launch_bounds__(256) void k_ns_init() {
    int g = blockIdx.y;
    int idx = blockIdx.x * 256 + threadIdx.x;
    int i = idx >> 9, j = idx & 511;
    float invc = 1.0f / (1.05f * g_scal[g]);
    float y = g_A[g][i][j] * invc;
    g_Y[0][g][i][j] = y;
    g_Z[0][g][i][j] = (i == j ? 1.5f : 0.0f) - 0.5f * y;
}

// ================= chain GEMM 512^3, FFMA2 (round-5 proven) =================
__global__ __launch_bounds__(256) void k_gemm512(int ida, int idb, int idc,
                                                 int mode, int rs, int ws) {
    int g = blockIdx.z;
    const float* A = bufptr(ida) + (size_t)g * LL * LL;
    const float* B = bufptr(idb) + (size_t)g * LL * LL;
    float* C = bufptr(idc) + (size_t)g * LL * LL;
    __shared__ float As[32][132];
    __shared__ float Bs[32][68];
    __shared__ float rsm[256];
    int t = threadIdx.x, tx = t & 15, ty = t >> 4;
    int i0 = blockIdx.y * 128, j0 = blockIdx.x * 64;
    float scale = 1.0f;
    if (mode == 2) {
        float fs = 0.f;
        #pragma unroll
        for (int q = 0; q < 32; q++) fs += g_red2[rs][g][q];
        scale = rsqrtf(fs);
    }
    u64 acc[4][4];
    #pragma unroll
    for (int u = 0; u < 4; u++)
        #pragma unroll
        for (int w = 0; w < 4; w++) acc[u][w] = 0ull;
    for (int kb = 0; kb < 512; kb += 32) {
        __syncthreads();
        #pragma unroll
        for (int q = 0; q < 4; q++) {
            int idx = t + 256 * q;
            int r = idx >> 3, c4 = (idx & 7) << 2;
            float4 av = *(const float4*)(A + (size_t)(i0 + r) * 512 + kb + c4);
            As[c4][r] = av.x; As[c4+1][r] = av.y; As[c4+2][r] = av.z; As[c4+3][r] = av.w;
        }
        #pragma unroll
        for (int q = 0; q < 2; q++) {
            int idx = t + 256 * q;
            int r2 = idx >> 4, d4 = (idx & 15) << 2;
            *(float4*)&Bs[r2][d4] = *(const float4*)(B + (size_t)(kb + r2) * 512 + j0 + d4);
        }
        __syncthreads();
        #pragma unroll
        for (int k = 0; k < 32; k++) {
            ulonglong2 a0 = *(const ulonglong2*)&As[k][ty * 8];
            ulonglong2 a1 = *(const ulonglong2*)&As[k][ty * 8 + 4];
            float4 bf = *(const float4*)&Bs[k][tx * 4];
            u64 s0 = splat2(bf.x), s1 = splat2(bf.y), s2 = splat2(bf.z), s3 = splat2(bf.w);
            u64 ar[4] = {a0.x, a0.y, a1.x, a1.y};
            #pragma unroll
            for (int u = 0; u < 4; u++) {
                acc[u][0] = ffma2(ar[u], s0, acc[u][0]);
                acc[u][1] = ffma2(ar[u], s1, acc[u][1]);
                acc[u][2] = ffma2(ar[u], s2, acc[u][2]);
                acc[u][3] = ffma2(ar[u], s3, acc[u][3]);
            }
        }
    }
    float ss = 0.f;
    #pragma unroll
    for (int u = 0; u < 4; u++) {
        int gia = i0 + ty * 8 + 2 * u;
        int gj = j0 + tx * 4;
        float2 f[4];
        #pragma unroll
        for (int w = 0; w < 4; w++) f[w] = unpk(acc[u][w]);
        float lo[4], hi[4];
        #pragma unroll
        for (int w = 0; w < 4; w++) {
            float va = f[w].x, vb = f[w].y;
            if (mode == 0) {
                va = (gia == gj + w ? 1.5f : 0.0f) - 0.5f * va;
                vb = (gia + 1 == gj + w ? 1.5f : 0.0f) - 0.5f * vb;
            } else if (mode == 2) {
                va *= scale; vb *= scale;
                ss += va * va + vb * vb;
            }
            lo[w] = va; hi[w] = vb;
        }
        *(float4*)&C[(size_t)gia * 512 + gj] = make_float4(lo[0], lo[1], lo[2], lo[3]);
        *(float4*)&C[(size_t)(gia + 1) * 512 + gj] = make_float4(hi[0], hi[1], hi[2], hi[3]);
    }
    if (mode == 2) {
        rsm[t] = ss; __syncthreads();
        for (int o = 128; o > 0; o >>= 1) { if (t < o) rsm[t] += rsm[t + o]; __syncthreads(); }
        if (t == 0) g_red2[ws][g][blockIdx.y * 8 + blockIdx.x] = rsm[0];
    }
}

// ================= M0 = sigma I - A + fnorm partials =================
__global__ __launch_bounds__(256) void k_shift() {
    int g = blockIdx.y;
    int base = blockIdx.x * 8192;
    float sigma = 1.15f * g_scal[g];
    float ss = 0.f;
    for (int q = 0; q < 32; q++) {
        int idx = base + threadIdx.x + 256 * q;
        int i = idx >> 9, j = idx & 511;
        float v = (i == j ? sigma : 0.0f) - g_A[g][i][j];
        g_M[0][g][i][j] = v;
        ss += v * v;
    }
    __shared__ float rsm[256];
    int t = threadIdx.x;
    rsm[t] = ss; __syncthreads();
    for (int o = 128; o > 0; o >>= 1) { if (t < o) rsm[t] += rsm[t + o]; __syncthreads(); }
    if (t == 0) g_red2[0][g][blockIdx.x] = rsm[0];
}

// ================= eigenvector extraction =================
__global__ void k_colnorm() {
    int g = blockIdx.x, j = threadIdx.x;
    const float* M = &g_M[0][g][0][0];
    float s = 0.f;
    for (int i = 0; i < LL; i++) { float m = M[(size_t)i * LL + j]; s += m * m; }
    __shared__ float sv[512]; __shared__ int si[512];
    sv[j] = s; si[j] = j; __syncthreads();
    for (int o = 256; o > 0; o >>= 1) {
        if (j < o) { if (sv[j + o] > sv[j]) { sv[j] = sv[j + o]; si[j] = si[j + o]; } }
        __syncthreads();
    }
    int jm = si[0];
    float inv = rsqrtf(sv[0]);
    g_v[g][j] = M[(size_t)j * LL + jm] * inv;
}

__global__ void k_rayleigh() {
    int g = blockIdx.x, i = threadIdx.x;
    __shared__ float vs[512];
    vs[i] = g_v[g][i]; __syncthreads();
    float u = 0.f;
    const float* Ac = &g_A[g][0][0];
    for (int k = 0; k < 512; k++) u = fmaf(Ac[(size_t)k * 512 + i], vs[k], u);
    __shared__ float r1[512], r2[512];
    r1[i] = u * vs[i]; r2[i] = vs[i] * vs[i]; __syncthreads();
    for (int o = 256; o > 0; o >>= 1) {
        if (i < o) { r1[i] += r1[i + o]; r2[i] += r2[i + o]; }
        __syncthreads();
    }
    if (i == 0) g_scal[8 + g] = r1[0] / r2[0];
}

// ================= P = Z/sqrt(c) - lam^{-1/2} v v^T (+ bf16 split) =================
__global__ __launch_bounds__(256) void k_subspace(int zid) {
    int g = blockIdx.y;
    int idx = blockIdx.x * 256 + threadIdx.x;
    int i = idx >> 9, j = idx & 511;
    const float* Z = bufptr(zid) + (size_t)g * LL * LL;
    float c = 1.05f * g_scal[g];
    float lam = g_scal[8 + g];
    float p = Z[(size_t)i * 512 + j] * rsqrtf(c) - rsqrtf(lam) * g_v[g][i] * g_v[g][j];
    g_P[g][i][j] = p;
    __nv_bfloat16 h = __float2bfloat16(p);
    gP_hi[g][i][j] = h;
    gP_lo[g][i][j] = __float2bfloat16(p - __bfloat162float(h));
}

// ================= beta = bias - w * (P mu) =================
__global__ void k_beta(const float* __restrict__ w, const float* __restrict__ b) {
    int g = blockIdx.x, i = threadIdx.x;
    __shared__ float mus[512];
    mus[i] = g_mu[g * LL + i]; __syncthreads();
    float s = 0.f;
    const float* Pc = &g_P[g][0][0];
    for (int k = 0; k < 512; k++) s = fmaf(Pc[(size_t)k * 512 + i], mus[k], s);
    int c = g * LL + i;
    g_beta[c] = b[c] - w[c] * s;
}

// ================= apply via mma.sync bf16 split =================
// out = w * (P X) + beta ; A = P (hi/lo, row-major), B = XT (hi/lo, n-major)
#define SRS 40   // smem row stride in bf16 elems (32 data + 8 pad)
__global__ __launch_bounds__(256) void k_apply_mma(const float* __restrict__ w,
                                                   float* __restrict__ out) {
    __shared__ __align__(16) unsigned short sAh[128 * SRS];
    __shared__ __align__(16) unsigned short sAl[128 * SRS];
    __shared__ __align__(16) unsigned short sBh[128 * SRS];
    __shared__ __align__(16) unsigned short sBl[128 * SRS];
    int t = threadIdx.x, lane = t & 31, wid = t >> 5;
    int wm = wid >> 2, wn = wid & 3;          // 2 x 4 warp grid, warp tile 64x32
    int n0 = blockIdx.x * 128, i0 = blockIdx.y * 128, g = blockIdx.z;

    const __nv_bfloat16* Ph = &gP_hi[g][0][0];
    const __nv_bfloat16* Pl = &gP_lo[g][0][0];
    const __nv_bfloat16* Xh = gXT_hi + (size_t)g * NT * LL;
    const __nv_bfloat16* Xl = gXT_lo + (size_t)g * NT * LL;

    float acc[4][4][4];
    #pragma unroll
    for (int mi = 0; mi < 4; mi++)
        #pragma unroll
        for (int ni = 0; ni < 4; ni++)
            #pragma unroll
            for (int e = 0; e < 4; e++) acc[mi][ni][e] = 0.f;

    // ldmatrix lane -> address offsets
    int aph = lane >> 3;
    int arow = (aph & 1) * 8 + (lane & 7);
    int acol = (aph >> 1) * 8;
    int brow = lane & 7;
    int bcol = ((lane >> 3) & 1) * 8;

    u32 bAh = smem_u32(sAh), bAl = smem_u32(sAl);
    u32 bBh = smem_u32(sBh), bBl = smem_u32(sBl);

    int ldr = t >> 2, ldc = (t & 3) * 8;     // loader: row, col-octet

    for (int ck = 0; ck < 16; ck++) {
        int k0 = ck * 32;
        __syncthreads();
        #pragma unroll
        for (int q = 0; q < 2; q++) {
            int r = ldr + q * 64;
            u32 so = r * SRS + ldc;
            *(uint4*)&sAh[so] = *(const uint4*)(Ph + (size_t)(i0 + r) * LL + k0 + ldc);
            *(uint4*)&sAl[so] = *(const uint4*)(Pl + (size_t)(i0 + r) * LL + k0 + ldc);
            *(uint4*)&sBh[so] = *(const uint4*)(Xh + (size_t)(n0 + r) * LL + k0 + ldc);
            *(uint4*)&sBl[so] = *(const uint4*)(Xl + (size_t)(n0 + r) * LL + k0 + ldc);
        }
        __syncthreads();
        #pragma unroll
        for (int kk = 0; kk < 32; kk += 16) {
            u32 Ahf[4][4], Alf[4][4];
            #pragma unroll
            for (int mi = 0; mi < 4; mi++) {
                u32 off = ((wm * 64 + mi * 16 + arow) * SRS + kk + acol) * 2;
                ldsm_x4(Ahf[mi][0], Ahf[mi][1], Ahf[mi][2], Ahf[mi][3], bAh + off);
                ldsm_x4(Alf[mi][0], Alf[mi][1], Alf[mi][2], Alf[mi][3], bAl + off);
            }
            #pragma unroll
            for (int ni = 0; ni < 4; ni++) {
                u32 off = ((wn * 32 + ni * 8 + brow) * SRS + kk + bcol) * 2;
                u32 bh0, bh1, bl0, bl1;
                ldsm_x2(bh0, bh1, bBh + off);
                ldsm_x2(bl0, bl1, bBl + off);
                #pragma unroll
                for (int mi = 0; mi < 4; mi++) {
                    mma_bf16(acc[mi][ni], Ahf[mi][0], Ahf[mi][1], Ahf[mi][2], Ahf[mi][3], bh0, bh1);
                    mma_bf16(acc[mi][ni], Ahf[mi][0], Ahf[mi][1], Ahf[mi][2], Ahf[mi][3], bl0, bl1);
                    mma_bf16(acc[mi][ni], Alf[mi][0], Alf[mi][1], Alf[mi][2], Alf[mi][3], bh0, bh1);
                }
            }
        }
    }

    // epilogue
    #pragma unroll
    for (int mi = 0; mi < 4; mi++) {
        int r0 = i0 + wm * 64 + mi * 16 + (lane >> 2);
        int ch0 = g * LL + r0, ch1 = ch0 + 8;
        float w0 = w[ch0], be0 = g_beta[ch0];
        float w1 = w[ch1], be1 = g_beta[ch1];
        #pragma unroll
        for (int ni = 0; ni < 4; ni++) {
            int col = n0 + wn * 32 + ni * 8 + 2 * (lane & 3);
            float2 v0, v1;
            v0.x = fmaf(w0, acc[mi][ni][0], be0);
            v0.y = fmaf(w0, acc[mi][ni][1], be0);
            v1.x = fmaf(w1, acc[mi][ni][2], be1);
            v1.y = fmaf(w1, acc[mi][ni][3], be1);
            *(float2*)(out + (size_t)ch0 * NT + col) = v0;
            *(float2*)(out + (size_t)ch1 * NT + col) = v1;
        }
    }
}

// ================= launch =================
extern "C" void kernel_launch(void* const* d_in, const int* in_sizes, int n_in,
                              void* d_out, int out_size) {
    const float* x = (const float*)d_in[0];
    const float* w = (const float*)d_in[1];
    const float* b = (const float*)d_in[2];
    float* out = (float*)d_out;

    k_mean<<<CC, 256>>>(x);
    k_cvt<<<dim3(128, 16, GG), 256>>>(x);
    k_cov<<<dim3(10, GG, KS), 256>>>(x);
    k_cov_reduce<<<dim3(1024, GG), 256>>>();

    k_pi_init<<<8, 256>>>();
    for (int m = 0; m < 7; m++)
        k_matvec<<<dim3(16, GG), 256>>>(m & 1);
    k_rq<<<GG, 512>>>();

    k_ns_init<<<dim3(1024, GG), 256>>>();
    dim3 gg(8, 4, GG);
    k_gemm512<<<gg, 256>>>(0, 2, 1, 1, 0, 0);   // Y1 = Y0 T0
    k_gemm512<<<gg, 256>>>(2, 1, 4, 0, 0, 0);   // T  = 1.5I - 0.5 Z1 Y1
    k_gemm512<<<gg, 256>>>(1, 4, 0, 1, 0, 0);   // Y2
    k_gemm512<<<gg, 256>>>(4, 2, 3, 1, 0, 0);   // Z2
    k_gemm512<<<gg, 256>>>(3, 0, 4, 0, 0, 0);   // T
    k_gemm512<<<gg, 256>>>(0, 4, 1, 1, 0, 0);   // Y3
    k_gemm512<<<gg, 256>>>(4, 3, 2, 1, 0, 0);   // Z3
    k_gemm512<<<gg, 256>>>(2, 1, 4, 0, 0, 0);   // T
    k_gemm512<<<gg, 256>>>(4, 2, 3, 1, 0, 0);   // Z4 -> buf 3 (final)

    k_shift<<<dim3(32, GG), 256>>>();
    for (int k = 0; k < SQ_ITERS; k++) {
        int inb = 5 + (k & 1), outb = 5 + 1 - (k & 1);
        k_gemm512<<<gg, 256>>>(inb, inb, outb, 2, k & 1, 1 - (k & 1));
    }

    k_colnorm<<<GG, 512>>>();
    k_rayleigh<<<GG, 512>>>();
    k_subspace<<<dim3(1024, GG), 256>>>(3);
    k_beta<<<GG, 512>>>(w, b);
    k_apply_mma<<<dim3(128, 4, GG), 256>>>(w, out);
}

// round 12
// speedup vs baseline: 1.5324x; 1.2039x over previous
#include <cuda_runtime.h>
#include <cuda_bf16.h>
#include <math.h>

#define CC 2048
#define GG 4
#define LL 512
#define NT 16384
#define EPSV 1e-4f
#define KS 16
#define KCH (NT/KS)
#define SQ_ITERS 12

typedef unsigned long long u64;
typedef unsigned int u32;
typedef unsigned short ush;

// ================= FFMA2 helpers =================
__device__ __forceinline__ u64 ffma2(u64 a, u64 b, u64 c) {
    u64 d;
    asm("fma.rn.f32x2 %0, %1, %2, %3;" : "=l"(d) : "l"(a), "l"(b), "l"(c));
    return d;
}
__device__ __forceinline__ u64 splat2(float x) {
    u64 d; unsigned xi = __float_as_uint(x);
    asm("mov.b64 %0, {%1, %2};" : "=l"(d) : "r"(xi), "r"(xi));
    return d;
}
__device__ __forceinline__ float2 unpk(u64 v) {
    unsigned lo, hi;
    asm("mov.b64 {%0, %1}, %2;" : "=r"(lo), "=r"(hi) : "l"(v));
    float2 r; r.x = __uint_as_float(lo); r.y = __uint_as_float(hi); return r;
}

// ================= mma.sync / ldmatrix helpers =================
__device__ __forceinline__ u32 smem_u32(const void* p) {
    u32 a;
    asm("{ .reg .u64 t; cvta.to.shared.u64 t, %1; cvt.u32.u64 %0, t; }" : "=r"(a) : "l"(p));
    return a;
}
__device__ __forceinline__ void ldsm_x4(u32& r0, u32& r1, u32& r2, u32& r3, u32 addr) {
    asm volatile("ldmatrix.sync.aligned.m8n8.x4.shared.b16 {%0,%1,%2,%3}, [%4];"
                 : "=r"(r0), "=r"(r1), "=r"(r2), "=r"(r3) : "r"(addr));
}
__device__ __forceinline__ void ldsm_x2(u32& r0, u32& r1, u32 addr) {
    asm volatile("ldmatrix.sync.aligned.m8n8.x2.shared.b16 {%0,%1}, [%2];"
                 : "=r"(r0), "=r"(r1) : "r"(addr));
}
__device__ __forceinline__ void mma_bf16(float* c, u32 a0, u32 a1, u32 a2, u32 a3,
                                         u32 b0, u32 b1) {
    asm volatile(
        "mma.sync.aligned.m16n8k16.row.col.f32.bf16.bf16.f32 "
        "{%0,%1,%2,%3}, {%4,%5,%6,%7}, {%8,%9}, {%0,%1,%2,%3};"
        : "+f"(c[0]), "+f"(c[1]), "+f"(c[2]), "+f"(c[3])
        : "r"(a0), "r"(a1), "r"(a2), "r"(a3), "r"(b0), "r"(b1));
}

// ================= device scratch =================
__device__ float g_part[KS][GG][LL][LL];
__device__ float g_A[GG][LL][LL];
__device__ float g_Y[2][GG][LL][LL];
__device__ float g_Z[2][GG][LL][LL];
__device__ float g_T[GG][LL][LL];
__device__ float g_M[2][GG][LL][LL];
__device__ float g_P[GG][LL][LL];
__device__ float g_mu[CC];
__device__ float g_pv[2][GG][LL];
__device__ float g_v[GG][LL];
__device__ float g_beta[CC];
__device__ float g_scal[16];
__device__ float g_red2[2][GG][32];
// bf16 split operands
__device__ __nv_bfloat16 gX_hi[(size_t)CC * NT];     // row-major (channel, n)
__device__ __nv_bfloat16 gX_lo[(size_t)CC * NT];
__device__ __nv_bfloat16 gXT_hi[(size_t)GG * NT * LL]; // n-major (n, k)
__device__ __nv_bfloat16 gXT_lo[(size_t)GG * NT * LL];
__device__ __nv_bfloat16 gP_hi[GG][LL][LL];
__device__ __nv_bfloat16 gP_lo[GG][LL][LL];

__device__ __forceinline__ float* bufptr(int id) {
    switch (id) {
        case 0: return &g_Y[0][0][0][0];
        case 1: return &g_Y[1][0][0][0];
        case 2: return &g_Z[0][0][0][0];
        case 3: return &g_Z[1][0][0][0];
        case 4: return &g_T[0][0][0];
        case 5: return &g_M[0][0][0][0];
        case 6: return &g_M[1][0][0][0];
        default: return &g_A[0][0][0];
    }
}

// ================= mean =================
__global__ __launch_bounds__(256) void k_mean(const float* __restrict__ x) {
    __shared__ float sm[256];
    int c = blockIdx.x;
    const float4* row = (const float4*)(x + (size_t)c * NT);
    float s = 0.f;
    for (int i = threadIdx.x; i < NT / 4; i += 256) {
        float4 v = row[i];
        s += (v.x + v.y) + (v.z + v.w);
    }
    int t = threadIdx.x;
    sm[t] = s; __syncthreads();
    for (int o = 128; o > 0; o >>= 1) { if (t < o) sm[t] += sm[t + o]; __syncthreads(); }
    if (t == 0) g_mu[c] = sm[0] * (1.f / NT);
}

// ================= X -> bf16 hi/lo row-major AND transposed =================
__global__ __launch_bounds__(256) void k_cvt(const float* __restrict__ x) {
    __shared__ float ts[32][129];
    int g = blockIdx.z, k0 = blockIdx.y * 32, n0 = blockIdx.x * 128;
    int t = threadIdx.x;
    #pragma unroll
    for (int q = 0; q < 16; q++) {
        int idx = t + 256 * q;
        int r = idx >> 7, c = idx & 127;
        size_t o = (size_t)(g * LL + k0 + r) * NT + n0 + c;
        float v = x[o];
        ts[r][c] = v;
        __nv_bfloat16 h = __float2bfloat16(v);
        __nv_bfloat16 l = __float2bfloat16(v - __bfloat162float(h));
        gX_hi[o] = h;
        gX_lo[o] = l;
    }
    __syncthreads();
    #pragma unroll
    for (int q = 0; q < 2; q++) {
        int task = t + 256 * q;
        int n = task >> 2, oct = task & 3;
        union { ush s[8]; uint4 v; } ph, pl;
        #pragma unroll
        for (int e = 0; e < 8; e++) {
            float vv = ts[oct * 8 + e][n];
            __nv_bfloat16 h = __float2bfloat16(vv);
            float hf = __bfloat162float(h);
            __nv_bfloat16 l = __float2bfloat16(vv - hf);
            ph.s[e] = *(ush*)&h;
            pl.s[e] = *(ush*)&l;
        }
        size_t dst = (size_t)(g * NT + n0 + n) * LL + k0 + oct * 8;
        *(uint4*)&gXT_hi[dst] = ph.v;
        *(uint4*)&gXT_lo[dst] = pl.v;
    }
}

#define SRS 40   // smem row stride in bf16 elems (32 data + 8 pad)

// ================= cov partials via mma.sync bf16 split =================
// g_part[sp][g][i][j] = sum_{n in split} X[i,n] X[j,n]
__global__ __launch_bounds__(256) void k_cov_mma() {
    __shared__ __align__(16) ush sAh[128 * SRS];
    __shared__ __align__(16) ush sAl[128 * SRS];
    __shared__ __align__(16) ush sBh[128 * SRS];
    __shared__ __align__(16) ush sBl[128 * SRS];
    const int TIa[10] = {0,1,1,2,2,2,3,3,3,3};
    const int TJa[10] = {0,0,1,0,1,2,0,1,2,3};
    int t = threadIdx.x, lane = t & 31, wid = t >> 5;
    int wm = wid >> 2, wn = wid & 3;
    int ti = TIa[blockIdx.x] * 128, tj = TJa[blockIdx.x] * 128;
    int g = blockIdx.y, sp = blockIdx.z;

    const __nv_bfloat16* Ah = gX_hi + (size_t)(g * LL + ti) * NT + sp * KCH;
    const __nv_bfloat16* Al = gX_lo + (size_t)(g * LL + ti) * NT + sp * KCH;
    const __nv_bfloat16* Bh = gX_hi + (size_t)(g * LL + tj) * NT + sp * KCH;
    const __nv_bfloat16* Bl = gX_lo + (size_t)(g * LL + tj) * NT + sp * KCH;

    float acc[4][4][4];
    #pragma unroll
    for (int mi = 0; mi < 4; mi++)
        #pragma unroll
        for (int ni = 0; ni < 4; ni++)
            #pragma unroll
            for (int e = 0; e < 4; e++) acc[mi][ni][e] = 0.f;

    int aph = lane >> 3;
    int arow = (aph & 1) * 8 + (lane & 7);
    int acol = (aph >> 1) * 8;
    int brow = lane & 7;
    int bcol = ((lane >> 3) & 1) * 8;

    u32 bAh = smem_u32(sAh), bAl = smem_u32(sAl);
    u32 bBh = smem_u32(sBh), bBl = smem_u32(sBl);

    int ldr = t >> 2, ldc = (t & 3) * 8;

    for (int ck = 0; ck < KCH / 32; ck++) {
        int k0 = ck * 32;
        __syncthreads();
        #pragma unroll
        for (int q = 0; q < 2; q++) {
            int r = ldr + q * 64;
            u32 so = r * SRS + ldc;
            *(uint4*)&sAh[so] = *(const uint4*)(Ah + (size_t)r * NT + k0 + ldc);
            *(uint4*)&sAl[so] = *(const uint4*)(Al + (size_t)r * NT + k0 + ldc);
            *(uint4*)&sBh[so] = *(const uint4*)(Bh + (size_t)r * NT + k0 + ldc);
            *(uint4*)&sBl[so] = *(const uint4*)(Bl + (size_t)r * NT + k0 + ldc);
        }
        __syncthreads();
        #pragma unroll
        for (int kk = 0; kk < 32; kk += 16) {
            u32 Ahf[4][4], Alf[4][4];
            #pragma unroll
            for (int mi = 0; mi < 4; mi++) {
                u32 off = ((wm * 64 + mi * 16 + arow) * SRS + kk + acol) * 2;
                ldsm_x4(Ahf[mi][0], Ahf[mi][1], Ahf[mi][2], Ahf[mi][3], bAh + off);
                ldsm_x4(Alf[mi][0], Alf[mi][1], Alf[mi][2], Alf[mi][3], bAl + off);
            }
            #pragma unroll
            for (int ni = 0; ni < 4; ni++) {
                u32 off = ((wn * 32 + ni * 8 + brow) * SRS + kk + bcol) * 2;
                u32 bh0, bh1, bl0, bl1;
                ldsm_x2(bh0, bh1, bBh + off);
                ldsm_x2(bl0, bl1, bBl + off);
                #pragma unroll
                for (int mi = 0; mi < 4; mi++) {
                    mma_bf16(acc[mi][ni], Ahf[mi][0], Ahf[mi][1], Ahf[mi][2], Ahf[mi][3], bh0, bh1);
                    mma_bf16(acc[mi][ni], Ahf[mi][0], Ahf[mi][1], Ahf[mi][2], Ahf[mi][3], bl0, bl1);
                    mma_bf16(acc[mi][ni], Alf[mi][0], Alf[mi][1], Alf[mi][2], Alf[mi][3], bh0, bh1);
                }
            }
        }
    }

    // epilogue: fp32 partials
    float* base = &g_part[sp][g][0][0];
    #pragma unroll
    for (int mi = 0; mi < 4; mi++) {
        int r0 = ti + wm * 64 + mi * 16 + (lane >> 2);
        #pragma unroll
        for (int ni = 0; ni < 4; ni++) {
            int col = tj + wn * 32 + ni * 8 + 2 * (lane & 3);
            *(float2*)(base + (size_t)r0 * LL + col) =
                make_float2(acc[mi][ni][0], acc[mi][ni][1]);
            *(float2*)(base + (size_t)(r0 + 8) * LL + col) =
                make_float2(acc[mi][ni][2], acc[mi][ni][3]);
        }
    }
}

// ================= reduce partials -> A =================
__global__ __launch_bounds__(256) void k_cov_reduce() {
    int g = blockIdx.y;
    int idx = blockIdx.x * 256 + threadIdx.x;
    int i = idx >> 9, j = idx & 511;
    if (i < j) return;
    float s = 0.f;
    #pragma unroll
    for (int sp = 0; sp < KS; sp++) s += g_part[sp][g][i][j];
    float v = s * (1.f / NT) - g_mu[g * LL + i] * g_mu[g * LL + j];
    if (i == j) v += EPSV;
    g_A[g][i][j] = v;
    g_A[g][j][i] = v;
}

// ================= power iteration =================
__global__ void k_pi_init() {
    int idx = blockIdx.x * 256 + threadIdx.x;
    if (idx < GG * LL) {
        unsigned h = (unsigned)idx * 1103515245u + 12345u;
        ((float*)g_pv)[idx] = 0.5f + (float)(h & 1023u) * (1.0f / 1024.0f);
    }
}

__global__ __launch_bounds__(256) void k_matvec(int inb) {
    int g = blockIdx.y;
    __shared__ float vs[LL];
    for (int i = threadIdx.x; i < LL; i += 256) vs[i] = g_pv[inb][g][i];
    __syncthreads();
    int warp = threadIdx.x >> 5, lane = threadIdx.x & 31;
    int row0 = blockIdx.x * 32 + warp * 4;
    for (int r = 0; r < 4; r++) {
        int i = row0 + r;
        const float* Ar = &g_A[g][i][0];
        float s = 0.f;
        for (int k = lane; k < LL; k += 32) s += Ar[k] * vs[k];
        #pragma unroll
        for (int o = 16; o > 0; o >>= 1) s += __shfl_down_sync(0xffffffffu, s, o);
        if (lane == 0) g_pv[1 - inb][g][i] = s;
    }
}

__global__ void k_rq() {
    int g = blockIdx.x, i = threadIdx.x;
    __shared__ float r1[512], r2[512];
    float v = g_pv[0][g][i], u = g_pv[1][g][i];
    r1[i] = v * u; r2[i] = v * v; __syncthreads();
    for (int o = 256; o > 0; o >>= 1) {
        if (i < o) { r1[i] += r1[i + o]; r2[i] += r2[i + o]; }
        __syncthreads();
    }
    if (i == 0) g_scal[g] = r1[0] / r2[0];
}

// ================= NS init =================
__global__ __launch_bounds__(256) void k_ns_init() {
    int g = blockIdx.y;
    int idx = blockIdx.x * 256 + threadIdx.x;
    int i = idx >> 9, j = idx & 511;
    float invc = 1.0f / (1.05f * g_scal[g]);
    float y = g_A[g][i][j] * invc;
    g_Y[0][g][i][j] = y;
    g_Z[0][g][i][j] = (i == j ? 1.5f : 0.0f) - 0.5f * y;
}

// ================= chain GEMM 512^3, FFMA2 (round-5 proven) =================
__global__ __launch_bounds__(256) void k_gemm512(int ida, int idb, int idc,
                                                 int mode, int rs, int ws) {
    int g = blockIdx.z;
    const float* A = bufptr(ida) + (size_t)g * LL * LL;
    const float* B = bufptr(idb) + (size_t)g * LL * LL;
    float* C = bufptr(idc) + (size_t)g * LL * LL;
    __shared__ float As[32][132];
    __shared__ float Bs[32][68];
    __shared__ float rsm[256];
    int t = threadIdx.x, tx = t & 15, ty = t >> 4;
    int i0 = blockIdx.y * 128, j0 = blockIdx.x * 64;
    float scale = 1.0f;
    if (mode == 2) {
        float fs = 0.f;
        #pragma unroll
        for (int q = 0; q < 32; q++) fs += g_red2[rs][g][q];
        scale = rsqrtf(fs);
    }
    u64 acc[4][4];
    #pragma unroll
    for (int u = 0; u < 4; u++)
        #pragma unroll
        for (int w = 0; w < 4; w++) acc[u][w] = 0ull;
    for (int kb = 0; kb < 512; kb += 32) {
        __syncthreads();
        #pragma unroll
        for (int q = 0; q < 4; q++) {
            int idx = t + 256 * q;
            int r = idx >> 3, c4 = (idx & 7) << 2;
            float4 av = *(const float4*)(A + (size_t)(i0 + r) * 512 + kb + c4);
            As[c4][r] = av.x; As[c4+1][r] = av.y; As[c4+2][r] = av.z; As[c4+3][r] = av.w;
        }
        #pragma unroll
        for (int q = 0; q < 2; q++) {
            int idx = t + 256 * q;
            int r2 = idx >> 4, d4 = (idx & 15) << 2;
            *(float4*)&Bs[r2][d4] = *(const float4*)(B + (size_t)(kb + r2) * 512 + j0 + d4);
        }
        __syncthreads();
        #pragma unroll
        for (int k = 0; k < 32; k++) {
            ulonglong2 a0 = *(const ulonglong2*)&As[k][ty * 8];
            ulonglong2 a1 = *(const ulonglong2*)&As[k][ty * 8 + 4];
            float4 bf = *(const float4*)&Bs[k][tx * 4];
            u64 s0 = splat2(bf.x), s1 = splat2(bf.y), s2 = splat2(bf.z), s3 = splat2(bf.w);
            u64 ar[4] = {a0.x, a0.y, a1.x, a1.y};
            #pragma unroll
            for (int u = 0; u < 4; u++) {
                acc[u][0] = ffma2(ar[u], s0, acc[u][0]);
                acc[u][1] = ffma2(ar[u], s1, acc[u][1]);
                acc[u][2] = ffma2(ar[u], s2, acc[u][2]);
                acc[u][3] = ffma2(ar[u], s3, acc[u][3]);
            }
        }
    }
    float ss = 0.f;
    #pragma unroll
    for (int u = 0; u < 4; u++) {
        int gia = i0 + ty * 8 + 2 * u;
        int gj = j0 + tx * 4;
        float2 f[4];
        #pragma unroll
        for (int w = 0; w < 4; w++) f[w] = unpk(acc[u][w]);
        float lo[4], hi[4];
        #pragma unroll
        for (int w = 0; w < 4; w++) {
            float va = f[w].x, vb = f[w].y;
            if (mode == 0) {
                va = (gia == gj + w ? 1.5f : 0.0f) - 0.5f * va;
                vb = (gia + 1 == gj + w ? 1.5f : 0.0f) - 0.5f * vb;
            } else if (mode == 2) {
                va *= scale; vb *= scale;
                ss += va * va + vb * vb;
            }
            lo[w] = va; hi[w] = vb;
        }
        *(float4*)&C[(size_t)gia * 512 + gj] = make_float4(lo[0], lo[1], lo[2], lo[3]);
        *(float4*)&C[(size_t)(gia + 1) * 512 + gj] = make_float4(hi[0], hi[1], hi[2], hi[3]);
    }
    if (mode == 2) {
        rsm[t] = ss; __syncthreads();
        for (int o = 128; o > 0; o >>= 1) { if (t < o) rsm[t] += rsm[t + o]; __syncthreads(); }
        if (t == 0) g_red2[ws][g][blockIdx.y * 8 + blockIdx.x] = rsm[0];
    }
}

// ================= M0 = sigma I - A + fnorm partials =================
__global__ __launch_bounds__(256) void k_shift() {
    int g = blockIdx.y;
    int base = blockIdx.x * 8192;
    float sigma = 1.15f * g_scal[g];
    float ss = 0.f;
    for (int q = 0; q < 32; q++) {
        int idx = base + threadIdx.x + 256 * q;
        int i = idx >> 9, j = idx & 511;
        float v = (i == j ? sigma : 0.0f) - g_A[g][i][j];
        g_M[0][g][i][j] = v;
        ss += v * v;
    }
    __shared__ float rsm[256];
    int t = threadIdx.x;
    rsm[t] = ss; __syncthreads();
    for (int o = 128; o > 0; o >>= 1) { if (t < o) rsm[t] += rsm[t + o]; __syncthreads(); }
    if (t == 0) g_red2[0][g][blockIdx.x] = rsm[0];
}

// ================= eigenvector extraction =================
__global__ void k_colnorm() {
    int g = blockIdx.x, j = threadIdx.x;
    const float* M = &g_M[0][g][0][0];
    float s = 0.f;
    for (int i = 0; i < LL; i++) { float m = M[(size_t)i * LL + j]; s += m * m; }
    __shared__ float sv[512]; __shared__ int si[512];
    sv[j] = s; si[j] = j; __syncthreads();
    for (int o = 256; o > 0; o >>= 1) {
        if (j < o) { if (sv[j + o] > sv[j]) { sv[j] = sv[j + o]; si[j] = si[j + o]; } }
        __syncthreads();
    }
    int jm = si[0];
    float inv = rsqrtf(sv[0]);
    g_v[g][j] = M[(size_t)j * LL + jm] * inv;
}

__global__ void k_rayleigh() {
    int g = blockIdx.x, i = threadIdx.x;
    __shared__ float vs[512];
    vs[i] = g_v[g][i]; __syncthreads();
    float u = 0.f;
    const float* Ac = &g_A[g][0][0];
    for (int k = 0; k < 512; k++) u = fmaf(Ac[(size_t)k * 512 + i], vs[k], u);
    __shared__ float r1[512], r2[512];
    r1[i] = u * vs[i]; r2[i] = vs[i] * vs[i]; __syncthreads();
    for (int o = 256; o > 0; o >>= 1) {
        if (i < o) { r1[i] += r1[i + o]; r2[i] += r2[i + o]; }
        __syncthreads();
    }
    if (i == 0) g_scal[8 + g] = r1[0] / r2[0];
}

// ================= P = Z/sqrt(c) - lam^{-1/2} v v^T (+ bf16 split) =================
__global__ __launch_bounds__(256) void k_subspace(int zid) {
    int g = blockIdx.y;
    int idx = blockIdx.x * 256 + threadIdx.x;
    int i = idx >> 9, j = idx & 511;
    const float* Z = bufptr(zid) + (size_t)g * LL * LL;
    float c = 1.05f * g_scal[g];
    float lam = g_scal[8 + g];
    float p = Z[(size_t)i * 512 + j] * rsqrtf(c) - rsqrtf(lam) * g_v[g][i] * g_v[g][j];
    g_P[g][i][j] = p;
    __nv_bfloat16 h = __float2bfloat16(p);
    gP_hi[g][i][j] = h;
    gP_lo[g][i][j] = __float2bfloat16(p - __bfloat162float(h));
}

// ================= beta = bias - w * (P mu) =================
__global__ void k_beta(const float* __restrict__ w, const float* __restrict__ b) {
    int g = blockIdx.x, i = threadIdx.x;
    __shared__ float mus[512];
    mus[i] = g_mu[g * LL + i]; __syncthreads();
    float s = 0.f;
    const float* Pc = &g_P[g][0][0];
    for (int k = 0; k < 512; k++) s = fmaf(Pc[(size_t)k * 512 + i], mus[k], s);
    int c = g * LL + i;
    g_beta[c] = b[c] - w[c] * s;
}

// ================= apply via mma.sync bf16 split (round-11 proven) =================
__global__ __launch_bounds__(256) void k_apply_mma(const float* __restrict__ w,
                                                   float* __restrict__ out) {
    __shared__ __align__(16) ush sAh[128 * SRS];
    __shared__ __align__(16) ush sAl[128 * SRS];
    __shared__ __align__(16) ush sBh[128 * SRS];
    __shared__ __align__(16) ush sBl[128 * SRS];
    int t = threadIdx.x, lane = t & 31, wid = t >> 5;
    int wm = wid >> 2, wn = wid & 3;
    int n0 = blockIdx.x * 128, i0 = blockIdx.y * 128, g = blockIdx.z;

    const __nv_bfloat16* Ph = &gP_hi[g][0][0];
    const __nv_bfloat16* Pl = &gP_lo[g][0][0];
    const __nv_bfloat16* Xh = gXT_hi + (size_t)g * NT * LL;
    const __nv_bfloat16* Xl = gXT_lo + (size_t)g * NT * LL;

    float acc[4][4][4];
    #pragma unroll
    for (int mi = 0; mi < 4; mi++)
        #pragma unroll
        for (int ni = 0; ni < 4; ni++)
            #pragma unroll
            for (int e = 0; e < 4; e++) acc[mi][ni][e] = 0.f;

    int aph = lane >> 3;
    int arow = (aph & 1) * 8 + (lane & 7);
    int acol = (aph >> 1) * 8;
    int brow = lane & 7;
    int bcol = ((lane >> 3) & 1) * 8;

    u32 bAh = smem_u32(sAh), bAl = smem_u32(sAl);
    u32 bBh = smem_u32(sBh), bBl = smem_u32(sBl);

    int ldr = t >> 2, ldc = (t & 3) * 8;

    for (int ck = 0; ck < 16; ck++) {
        int k0 = ck * 32;
        __syncthreads();
        #pragma unroll
        for (int q = 0; q < 2; q++) {
            int r = ldr + q * 64;
            u32 so = r * SRS + ldc;
            *(uint4*)&sAh[so] = *(const uint4*)(Ph + (size_t)(i0 + r) * LL + k0 + ldc);
            *(uint4*)&sAl[so] = *(const uint4*)(Pl + (size_t)(i0 + r) * LL + k0 + ldc);
            *(uint4*)&sBh[so] = *(const uint4*)(Xh + (size_t)(n0 + r) * LL + k0 + ldc);
            *(uint4*)&sBl[so] = *(const uint4*)(Xl + (size_t)(n0 + r) * LL + k0 + ldc);
        }
        __syncthreads();
        #pragma unroll
        for (int kk = 0; kk < 32; kk += 16) {
            u32 Ahf[4][4], Alf[4][4];
            #pragma unroll
            for (int mi = 0; mi < 4; mi++) {
                u32 off = ((wm * 64 + mi * 16 + arow) * SRS + kk + acol) * 2;
                ldsm_x4(Ahf[mi][0], Ahf[mi][1], Ahf[mi][2], Ahf[mi][3], bAh + off);
                ldsm_x4(Alf[mi][0], Alf[mi][1], Alf[mi][2], Alf[mi][3], bAl + off);
            }
            #pragma unroll
            for (int ni = 0; ni < 4; ni++) {
                u32 off = ((wn * 32 + ni * 8 + brow) * SRS + kk + bcol) * 2;
                u32 bh0, bh1, bl0, bl1;
                ldsm_x2(bh0, bh1, bBh + off);
                ldsm_x2(bl0, bl1, bBl + off);
                #pragma unroll
                for (int mi = 0; mi < 4; mi++) {
                    mma_bf16(acc[mi][ni], Ahf[mi][0], Ahf[mi][1], Ahf[mi][2], Ahf[mi][3], bh0, bh1);
                    mma_bf16(acc[mi][ni], Ahf[mi][0], Ahf[mi][1], Ahf[mi][2], Ahf[mi][3], bl0, bl1);
                    mma_bf16(acc[mi][ni], Alf[mi][0], Alf[mi][1], Alf[mi][2], Alf[mi][3], bh0, bh1);
                }
            }
        }
    }

    #pragma unroll
    for (int mi = 0; mi < 4; mi++) {
        int r0 = i0 + wm * 64 + mi * 16 + (lane >> 2);
        int ch0 = g * LL + r0, ch1 = ch0 + 8;
        float w0 = w[ch0], be0 = g_beta[ch0];
        float w1 = w[ch1], be1 = g_beta[ch1];
        #pragma unroll
        for (int ni = 0; ni < 4; ni++) {
            int col = n0 + wn * 32 + ni * 8 + 2 * (lane & 3);
            float2 v0, v1;
            v0.x = fmaf(w0, acc[mi][ni][0], be0);
            v0.y = fmaf(w0, acc[mi][ni][1], be0);
            v1.x = fmaf(w1, acc[mi][ni][2], be1);
            v1.y = fmaf(w1, acc[mi][ni][3], be1);
            *(float2*)(out + (size_t)ch0 * NT + col) = v0;
            *(float2*)(out + (size_t)ch1 * NT + col) = v1;
        }
    }
}

// ================= launch =================
extern "C" void kernel_launch(void* const* d_in, const int* in_sizes, int n_in,
                              void* d_out, int out_size) {
    const float* x = (const float*)d_in[0];
    const float* w = (const float*)d_in[1];
    const float* b = (const float*)d_in[2];
    float* out = (float*)d_out;

    k_mean<<<CC, 256>>>(x);
    k_cvt<<<dim3(128, 16, GG), 256>>>(x);
    k_cov_mma<<<dim3(10, GG, KS), 256>>>();
    k_cov_reduce<<<dim3(1024, GG), 256>>>();

    k_pi_init<<<8, 256>>>();
    for (int m = 0; m < 7; m++)
        k_matvec<<<dim3(16, GG), 256>>>(m & 1);
    k_rq<<<GG, 512>>>();

    k_ns_init<<<dim3(1024, GG), 256>>>();
    dim3 gg(8, 4, GG);
    k_gemm512<<<gg, 256>>>(0, 2, 1, 1, 0, 0);   // Y1 = Y0 T0
    k_gemm512<<<gg, 256>>>(2, 1, 4, 0, 0, 0);   // T  = 1.5I - 0.5 Z1 Y1
    k_gemm512<<<gg, 256>>>(1, 4, 0, 1, 0, 0);   // Y2
    k_gemm512<<<gg, 256>>>(4, 2, 3, 1, 0, 0);   // Z2
    k_gemm512<<<gg, 256>>>(3, 0, 4, 0, 0, 0);   // T
    k_gemm512<<<gg, 256>>>(0, 4, 1, 1, 0, 0);   // Y3
    k_gemm512<<<gg, 256>>>(4, 3, 2, 1, 0, 0);   // Z3
    k_gemm512<<<gg, 256>>>(2, 1, 4, 0, 0, 0);   // T
    k_gemm512<<<gg, 256>>>(4, 2, 3, 1, 0, 0);   // Z4 -> buf 3 (final)

    k_shift<<<dim3(32, GG), 256>>>();
    for (int k = 0; k < SQ_ITERS; k++) {
        int inb = 5 + (k & 1), outb = 5 + 1 - (k & 1);
        k_gemm512<<<gg, 256>>>(inb, inb, outb, 2, k & 1, 1 - (k & 1));
    }

    k_colnorm<<<GG, 512>>>();
    k_rayleigh<<<GG, 512>>>();
    k_subspace<<<dim3(1024, GG), 256>>>(3);
    k_beta<<<GG, 512>>>(w, b);
    k_apply_mma<<<dim3(128, 4, GG), 256>>>(w, out);
}